// round 9
// baseline (speedup 1.0000x reference)
#include <cuda_runtime.h>

// Problem constants (fixed by setup_inputs)
#define F_DIM    16384
#define BINS     128
#define FEAT     (2*BINS + 1)     // 257
#define OUT_DIM  64
#define MAXB     4096

// ---- kernel 1: per-row histogram features ----
#define NTHREADS 512
#define NWARPS   (NTHREADS/32)    // 16
#define VPT      (F_DIM/NTHREADS) // 32 values per thread (8 float4)

// feats scratch: [B, 257] fp32 (static device global; no allocation)
__device__ float g_feats[(size_t)MAXB * FEAT];

extern __shared__ unsigned char smem_raw[];

__global__ __launch_bounds__(NTHREADS)
void hist_feats_kernel(const float* __restrict__ x)
{
    // smem: per-warp histograms + warp min/max partials (no data staging:
    // each thread re-bins its own register-resident values)
    int*   s_hist = (int*)smem_raw;                       // 16*128 ints = 8192 B
    float* s_wmin = (float*)(smem_raw + (size_t)NWARPS * BINS * 4);
    float* s_wmax = s_wmin + NWARPS;

    const int t    = threadIdx.x;
    const int wid  = t >> 5;
    const int lane = t & 31;
    const int row  = blockIdx.x;

    // zero per-warp histograms
    #pragma unroll
    for (int i = t; i < NWARPS * BINS; i += NTHREADS) s_hist[i] = 0;

    // Pass A: stream row HBM -> registers (float4), track min/max in flight
    const float4* xr = (const float4*)(x + (size_t)row * F_DIM);
    float4 v[VPT / 4];
    float lmin =  3.402823e38f;
    float lmax = -3.402823e38f;
    #pragma unroll
    for (int k = 0; k < VPT / 4; k++) {
        v[k] = xr[t + k * NTHREADS];
        lmin = fminf(lmin, fminf(fminf(v[k].x, v[k].y), fminf(v[k].z, v[k].w)));
        lmax = fmaxf(lmax, fmaxf(fmaxf(v[k].x, v[k].y), fmaxf(v[k].z, v[k].w)));
    }
    // warp reduce min/max
    #pragma unroll
    for (int s = 16; s; s >>= 1) {
        lmin = fminf(lmin, __shfl_xor_sync(0xffffffffu, lmin, s));
        lmax = fmaxf(lmax, __shfl_xor_sync(0xffffffffu, lmax, s));
    }
    if (lane == 0) { s_wmin[wid] = lmin; s_wmax[wid] = lmax; }
    __syncthreads();

    // block min/max
    float mn = s_wmin[0], mx = s_wmax[0];
    #pragma unroll
    for (int i = 1; i < NWARPS; i++) {
        mn = fminf(mn, s_wmin[i]);
        mx = fmaxf(mx, s_wmax[i]);
    }
    const float width = mx - mn;
    const float scale = (width > 0.0f) ? ((float)BINS / width) : 0.0f;

    // Pass B: histogram straight from registers, per-warp privatized counters
    int* hw = s_hist + wid * BINS;
    #pragma unroll
    for (int k = 0; k < VPT / 4; k++) {
        // (v - mn) >= 0 always, so int-truncation == floor; clamp top bin
        int b0 = min(BINS - 1, (int)((v[k].x - mn) * scale));
        int b1 = min(BINS - 1, (int)((v[k].y - mn) * scale));
        int b2 = min(BINS - 1, (int)((v[k].z - mn) * scale));
        int b3 = min(BINS - 1, (int)((v[k].w - mn) * scale));
        atomicAdd(&hw[b0], 1);
        atomicAdd(&hw[b1], 1);
        atomicAdd(&hw[b2], 1);
        atomicAdd(&hw[b3], 1);
    }
    __syncthreads();

    // reduce per-warp histograms + emit feats row
    float* outf = g_feats + (size_t)row * FEAT;
    if (t < BINS) {
        int c = 0;
        #pragma unroll
        for (int w = 0; w < NWARPS; w++) c += s_hist[w * BINS + t];
        outf[t] = (float)c * (1.0f / (float)F_DIM);   // density: sum == F exactly
    } else if (t < BINS + BINS + 1) {
        int i = t - BINS;
        outf[BINS + i] = mn + ((float)i * (1.0f / (float)BINS)) * width;
    }
}

// ---- kernel 2: out[B,64] = feats[B,257] @ W^T + b ----
// M-tile 16 -> grid 256 -> 2 blocks/SM (occupancy), packed fma.rn.f32x2
// mainloop (2 k's per FFMA2). Smem rows padded to stride 258 (even, zero pad)
// so all operands are aligned LDS.64. A-frags warp-broadcast; B-frags at rows
// c and c+32 -> 2-way pair conflict = natural 64-bit LDS floor.
#define K2_TM    16
#define K2_T     256
#define KPAD     258                       // FEAT padded to even, pad elem = 0
#define NKP      (KPAD/2)                  // 129 k-pairs

typedef unsigned long long ull;

__device__ __forceinline__ void ffma2(ull& acc, ull a, ull b) {
    asm("fma.rn.f32x2 %0, %1, %2, %0;" : "+l"(acc) : "l"(a), "l"(b));
}
__device__ __forceinline__ float hsum_f32x2(ull v) {
    unsigned lo, hi;
    asm("mov.b64 {%0, %1}, %2;" : "=r"(lo), "=r"(hi) : "l"(v));
    return __uint_as_float(lo) + __uint_as_float(hi);
}

__global__ __launch_bounds__(K2_T)
void feats_gemm_kernel(const float* __restrict__ W,
                       const float* __restrict__ bias,
                       float* __restrict__ out, int B)
{
    float* sW = (float*)smem_raw;             // 64 rows * 258 = 16512 f (66048 B)
    float* sF = sW + OUT_DIM * KPAD;          // 16 rows * 258 (offset 16B-aligned)

    const int t    = threadIdx.x;
    const int wid  = t >> 5;                  // 0..7
    const int lane = t & 31;
    const int row0 = blockIdx.x * K2_TM;

    // stage W: warp wid copies rows wid*8 .. wid*8+7 (coalesced, no division)
    #pragma unroll
    for (int rr = 0; rr < 8; rr++) {
        const int o = wid * 8 + rr;
        const float* src = W + o * FEAT;
        float* dst = sW + o * KPAD;
        #pragma unroll
        for (int j = 0; j < 8; j++) dst[lane + j * 32] = src[lane + j * 32]; // 256
        if (lane == 0) { dst[256] = src[256]; dst[257] = 0.0f; }
    }
    // stage feats: warp wid copies rows wid*2, wid*2+1
    #pragma unroll
    for (int rr = 0; rr < 2; rr++) {
        const int r = wid * 2 + rr;
        if (row0 + r < B) {
            const float* src = g_feats + (size_t)(row0 + r) * FEAT;
            float* dst = sF + r * KPAD;
            #pragma unroll
            for (int j = 0; j < 8; j++) dst[lane + j * 32] = src[lane + j * 32];
            if (lane == 0) { dst[256] = src[256]; dst[257] = 0.0f; }
        }
    }
    __syncthreads();

    // each thread: 2 rows (wid*2, wid*2+1) x 2 cols (c, c+32)
    const int c = lane;
    const float* fa0 = sF + (wid * 2) * KPAD;       // broadcast (same addr per warp)
    const float* fa1 = fa0 + KPAD;
    const float* wc0 = sW + c * KPAD;
    const float* wc1 = sW + (c + 32) * KPAD;

    ull acc00 = 0ull, acc01 = 0ull, acc10 = 0ull, acc11 = 0ull;

    #pragma unroll 3
    for (int kp = 0; kp < NKP; kp++) {
        ull a0 = *(const ull*)(fa0 + 2 * kp);
        ull a1 = *(const ull*)(fa1 + 2 * kp);
        ull b0 = *(const ull*)(wc0 + 2 * kp);
        ull b1 = *(const ull*)(wc1 + 2 * kp);
        ffma2(acc00, a0, b0);  ffma2(acc01, a0, b1);
        ffma2(acc10, a1, b0);  ffma2(acc11, a1, b1);
    }

    const float bb0 = bias[c];
    const float bb1 = bias[c + 32];
    const int r0 = row0 + wid * 2;
    if (r0 < B) {
        out[(size_t)r0 * OUT_DIM + c]      = hsum_f32x2(acc00) + bb0;
        out[(size_t)r0 * OUT_DIM + c + 32] = hsum_f32x2(acc01) + bb1;
    }
    if (r0 + 1 < B) {
        out[(size_t)(r0 + 1) * OUT_DIM + c]      = hsum_f32x2(acc10) + bb0;
        out[(size_t)(r0 + 1) * OUT_DIM + c + 32] = hsum_f32x2(acc11) + bb1;
    }
}

extern "C" void kernel_launch(void* const* d_in, const int* in_sizes, int n_in,
                              void* d_out, int out_size)
{
    const float* x = (const float*)d_in[0];
    const float* W = (const float*)d_in[1];
    const float* b = (const float*)d_in[2];
    float* out = (float*)d_out;

    const int B = in_sizes[0] / F_DIM;

    const size_t sm1 = (size_t)NWARPS * BINS * 4 + 2 * NWARPS * 4;        // 8320 B
    const size_t sm2 = (size_t)(OUT_DIM + K2_TM) * KPAD * 4;              // 82560 B

    cudaFuncSetAttribute(hist_feats_kernel,
                         cudaFuncAttributeMaxDynamicSharedMemorySize, (int)sm1);
    cudaFuncSetAttribute(feats_gemm_kernel,
                         cudaFuncAttributeMaxDynamicSharedMemorySize, (int)sm2);

    hist_feats_kernel<<<B, NTHREADS, sm1>>>(x);
    feats_gemm_kernel<<<(B + K2_TM - 1) / K2_TM, K2_T, sm2>>>(W, b, out, B);
}

// round 11
// speedup vs baseline: 1.0764x; 1.0764x over previous
#include <cuda_runtime.h>

// Problem constants (fixed by setup_inputs)
#define F_DIM    16384
#define BINS     128
#define FEAT     (2*BINS + 1)     // 257
#define OUT_DIM  64
#define MAXB     4096

// ---- kernel 1: per-row histogram features ----
#define NTHREADS 512
#define NWARPS   (NTHREADS/32)    // 16
#define VPT      (F_DIM/NTHREADS) // 32 values per thread (8 float4)

// feats scratch: [B, 257] fp32 (static device global; no allocation)
__device__ float g_feats[(size_t)MAXB * FEAT];

extern __shared__ unsigned char smem_raw[];

__global__ __launch_bounds__(NTHREADS)
void hist_feats_kernel(const float* __restrict__ x)
{
    // smem: per-warp histograms + warp min/max partials (no data staging:
    // each thread re-bins its own register-resident values)
    int*   s_hist = (int*)smem_raw;                       // 16*128 ints = 8192 B
    float* s_wmin = (float*)(smem_raw + (size_t)NWARPS * BINS * 4);
    float* s_wmax = s_wmin + NWARPS;

    const int t    = threadIdx.x;
    const int wid  = t >> 5;
    const int lane = t & 31;
    const int row  = blockIdx.x;

    // zero per-warp histograms
    #pragma unroll
    for (int i = t; i < NWARPS * BINS; i += NTHREADS) s_hist[i] = 0;

    // Pass A: stream row HBM -> registers (float4), track min/max in flight
    const float4* xr = (const float4*)(x + (size_t)row * F_DIM);
    float4 v[VPT / 4];
    float lmin =  3.402823e38f;
    float lmax = -3.402823e38f;
    #pragma unroll
    for (int k = 0; k < VPT / 4; k++) {
        v[k] = xr[t + k * NTHREADS];
        lmin = fminf(lmin, fminf(fminf(v[k].x, v[k].y), fminf(v[k].z, v[k].w)));
        lmax = fmaxf(lmax, fmaxf(fmaxf(v[k].x, v[k].y), fmaxf(v[k].z, v[k].w)));
    }
    // warp reduce min/max
    #pragma unroll
    for (int s = 16; s; s >>= 1) {
        lmin = fminf(lmin, __shfl_xor_sync(0xffffffffu, lmin, s));
        lmax = fmaxf(lmax, __shfl_xor_sync(0xffffffffu, lmax, s));
    }
    if (lane == 0) { s_wmin[wid] = lmin; s_wmax[wid] = lmax; }
    __syncthreads();

    // block min/max
    float mn = s_wmin[0], mx = s_wmax[0];
    #pragma unroll
    for (int i = 1; i < NWARPS; i++) {
        mn = fminf(mn, s_wmin[i]);
        mx = fmaxf(mx, s_wmax[i]);
    }
    const float width = mx - mn;
    const float scale = (width > 0.0f) ? ((float)BINS / width) : 0.0f;
    const float base  = -mn * scale;   // bin = (int)fmaf(v, scale, base)

    // Pass B: histogram straight from registers, per-warp privatized counters.
    // One FMA + F2I + IMNMX + ATOMS per element. fmaf(v,scale,base) error vs
    // (v-mn)*scale is ~ulp(64) << 1 bin; truncation keeps idx >= 0.
    int* hw = s_hist + wid * BINS;
    #pragma unroll
    for (int k = 0; k < VPT / 4; k++) {
        int b0 = min(BINS - 1, (int)fmaf(v[k].x, scale, base));
        int b1 = min(BINS - 1, (int)fmaf(v[k].y, scale, base));
        int b2 = min(BINS - 1, (int)fmaf(v[k].z, scale, base));
        int b3 = min(BINS - 1, (int)fmaf(v[k].w, scale, base));
        atomicAdd(&hw[b0], 1);
        atomicAdd(&hw[b1], 1);
        atomicAdd(&hw[b2], 1);
        atomicAdd(&hw[b3], 1);
    }
    __syncthreads();

    // reduce per-warp histograms + emit feats row
    float* outf = g_feats + (size_t)row * FEAT;
    if (t < BINS) {
        int c = 0;
        #pragma unroll
        for (int w = 0; w < NWARPS; w++) c += s_hist[w * BINS + t];
        outf[t] = (float)c * (1.0f / (float)F_DIM);   // density: sum == F exactly
    } else if (t < BINS + BINS + 1) {
        int i = t - BINS;
        outf[BINS + i] = mn + ((float)i * (1.0f / (float)BINS)) * width;
    }
}

// ---- kernel 2: out[B,64] = feats[B,257] @ W^T + b ----
// M=32 tile, 512 threads (16 warps -> 4/SMSP for latency hiding), natural
// row-major smem tiles at ODD stride 257:
//   B-frags: scalar LDS at rows c and c+32 -> bank (c+k)%32, conflict-free.
//   A-frags: scalar LDS, same address warp-wide -> broadcast.
// Each thread: 2 rows (wid*2, wid*2+1) x 2 cols (c, c+32); 8 issues / 4 FMA per k.
#define K2_TM   32
#define K2_T    512

__global__ __launch_bounds__(K2_T)
void feats_gemm_kernel(const float* __restrict__ W,
                       const float* __restrict__ bias,
                       float* __restrict__ out, int B)
{
    float* sW = (float*)smem_raw;             // 64 * 257 f = 65792 B
    float* sF = sW + OUT_DIM * FEAT;          // 32 * 257 f = 32896 B

    const int t    = threadIdx.x;
    const int wid  = t >> 5;                  // 0..15
    const int lane = t & 31;
    const int row0 = blockIdx.x * K2_TM;

    // stage W: warp wid copies rows wid*4 .. wid*4+3 (coalesced, no division)
    #pragma unroll
    for (int rr = 0; rr < 4; rr++) {
        const int o = wid * 4 + rr;
        const float* src = W + o * FEAT;
        float* dst = sW + o * FEAT;
        #pragma unroll
        for (int j = 0; j < 8; j++) dst[lane + j * 32] = src[lane + j * 32]; // 256
        if (lane == 0) dst[256] = src[256];
    }
    // stage feats: warp wid copies rows wid*2, wid*2+1
    #pragma unroll
    for (int rr = 0; rr < 2; rr++) {
        const int r = wid * 2 + rr;
        if (row0 + r < B) {
            const float* src = g_feats + (size_t)(row0 + r) * FEAT;
            float* dst = sF + r * FEAT;
            #pragma unroll
            for (int j = 0; j < 8; j++) dst[lane + j * 32] = src[lane + j * 32];
            if (lane == 0) dst[256] = src[256];
        }
    }
    __syncthreads();

    const int c = lane;
    const float* fa0 = sF + (wid * 2) * FEAT;       // broadcast (same addr per warp)
    const float* fa1 = fa0 + FEAT;
    const float* w0  = sW + c * FEAT;               // conflict-free (odd stride)
    const float* w1  = sW + (c + 32) * FEAT;

    float acc00 = 0.f, acc01 = 0.f, acc10 = 0.f, acc11 = 0.f;

    #pragma unroll 4
    for (int k = 0; k < FEAT; k++) {
        float b0 = w0[k];
        float b1 = w1[k];
        float a0 = fa0[k];
        float a1 = fa1[k];
        acc00 = fmaf(a0, b0, acc00);  acc01 = fmaf(a0, b1, acc01);
        acc10 = fmaf(a1, b0, acc10);  acc11 = fmaf(a1, b1, acc11);
    }

    const float bb0 = bias[c];
    const float bb1 = bias[c + 32];
    const int r0 = row0 + wid * 2;
    if (r0 < B) {
        out[(size_t)r0 * OUT_DIM + c]      = acc00 + bb0;
        out[(size_t)r0 * OUT_DIM + c + 32] = acc01 + bb1;
    }
    if (r0 + 1 < B) {
        out[(size_t)(r0 + 1) * OUT_DIM + c]      = acc10 + bb0;
        out[(size_t)(r0 + 1) * OUT_DIM + c + 32] = acc11 + bb1;
    }
}

extern "C" void kernel_launch(void* const* d_in, const int* in_sizes, int n_in,
                              void* d_out, int out_size)
{
    const float* x = (const float*)d_in[0];
    const float* W = (const float*)d_in[1];
    const float* b = (const float*)d_in[2];
    float* out = (float*)d_out;

    const int B = in_sizes[0] / F_DIM;

    const size_t sm1 = (size_t)NWARPS * BINS * 4 + 2 * NWARPS * 4;        // 8320 B
    const size_t sm2 = (size_t)(OUT_DIM + K2_TM) * FEAT * 4;              // 98688 B

    cudaFuncSetAttribute(hist_feats_kernel,
                         cudaFuncAttributeMaxDynamicSharedMemorySize, (int)sm1);
    cudaFuncSetAttribute(feats_gemm_kernel,
                         cudaFuncAttributeMaxDynamicSharedMemorySize, (int)sm2);

    hist_feats_kernel<<<B, NTHREADS, sm1>>>(x);
    feats_gemm_kernel<<<(B + K2_TM - 1) / K2_TM, K2_T, sm2>>>(W, b, out, B);
}